// round 1
// baseline (speedup 1.0000x reference)
#include <cuda_runtime.h>
#include <cuda_bf16.h>
#include <cstdio>

// Problem constants (fixed shapes from reference)
#define BATCH 8
#define HH 96
#define WW 96
#define CC 128
#define LL (HH*WW)            // 9216
#define ROWS (BATCH*LL)       // 73728
#define NWIN 144              // 12*12 windows per image
#define WS 8
#define NTOK 64               // ws*ws
#define HEADS 4
#define HD 32
#define QKSCALE 0.17677669529663687f   // 32^-0.5

// ---------------- scratch (static device arrays; no allocation) -------------
__device__ float g_xw [ (size_t)ROWS*CC ];    // LN/gather output; reused as LN2 output
__device__ float g_qkv[ (size_t)ROWS*3*CC ];  // qkv
__device__ float g_att[ (size_t)ROWS*CC ];    // attention out; reused as patch-merge xc (18432*512, same size)
__device__ float g_xa [ (size_t)ROWS*CC ];    // x after block a
__device__ float g_xb [ (size_t)ROWS*CC ];    // x after block b
__device__ float g_h  [ (size_t)ROWS*4*CC ];  // MLP hidden

// ---------------- LayerNorm (+ optional window-gather w/ shift) -------------
// One warp per row of 128. GATHER=true: output row r is window-layout, source
// row is (h0+shift)%96,(w0+shift)%96 of the input image (xg = roll(x,-shift)).
template<bool GATHER>
__global__ __launch_bounds__(128) void ln_kernel(
    const float* __restrict__ x, const float* __restrict__ gam,
    const float* __restrict__ bet, float* __restrict__ out, int shift)
{
    int lane = threadIdx.x & 31;
    int warp = threadIdx.x >> 5;
    int r = blockIdx.x * 4 + warp;

    const float* src;
    if (GATHER) {
        int wi = r >> 6, n = r & 63;
        int b  = wi / NWIN, wl = wi % NWIN;
        int whi = wl / 12, wwi = wl % 12;
        int h0 = whi * 8 + (n >> 3), w0 = wwi * 8 + (n & 7);
        int hs = h0 + shift; if (hs >= HH) hs -= HH;
        int ws_ = w0 + shift; if (ws_ >= WW) ws_ -= WW;
        src = &x[(size_t)(b * LL + hs * WW + ws_) * CC];
    } else {
        src = &x[(size_t)r * CC];
    }
    float4 v = *(const float4*)&src[lane * 4];
    float s1 = v.x + v.y + v.z + v.w;
    float s2 = v.x*v.x + v.y*v.y + v.z*v.z + v.w*v.w;
    #pragma unroll
    for (int o = 16; o; o >>= 1) {
        s1 += __shfl_xor_sync(0xffffffffu, s1, o);
        s2 += __shfl_xor_sync(0xffffffffu, s2, o);
    }
    float mean = s1 * (1.f / CC);
    float var  = s2 * (1.f / CC) - mean * mean;
    float rstd = rsqrtf(var + 1e-5f);
    float4 g4 = *(const float4*)&gam[lane * 4];
    float4 b4 = *(const float4*)&bet[lane * 4];
    float4 o4;
    o4.x = (v.x - mean) * rstd * g4.x + b4.x;
    o4.y = (v.y - mean) * rstd * g4.y + b4.y;
    o4.z = (v.z - mean) * rstd * g4.z + b4.z;
    o4.w = (v.w - mean) * rstd * g4.w + b4.w;
    *(float4*)&out[(size_t)r * CC + lane * 4] = o4;
}

// ---------------- generic tiled SGEMM with fused epilogues ------------------
// C[M,N] = A[M,K] @ B[K,N]  (+bias)   epilogues:
//  EPI 0: +bias, plain store
//  EPI 1: +bias, window-reverse + roll(+shift) scatter, += residual (proj)
//  EPI 2: +bias, exact GELU (fc1)
//  EPI 3: +bias, += residual at same row (fc2, in-place-safe)
//  EPI 4: no bias, plain store (patch-merge reduction)
#define BM 128
#define BN 64
#define BKK 16

__device__ __forceinline__ float gelu_exact(float x) {
    return 0.5f * x * (1.f + erff(x * 0.70710678118654752f));
}

template<int EPI>
__global__ __launch_bounds__(256) void gemm_kernel(
    const float* __restrict__ A, const float* __restrict__ B,
    const float* __restrict__ bias, float* __restrict__ C,
    const float* __restrict__ res, int M, int N, int K, int shift)
{
    __shared__ float As[BKK][BM];
    __shared__ float Bs[BKK][BN];
    int tid = threadIdx.x;
    int tx = tid & 15, ty = tid >> 4;      // 16x16 threads
    int bm = blockIdx.x * BM, bn = blockIdx.y * BN;

    float acc[8][4];
    #pragma unroll
    for (int i = 0; i < 8; i++)
        #pragma unroll
        for (int j = 0; j < 4; j++) acc[i][j] = 0.f;

    for (int k0 = 0; k0 < K; k0 += BKK) {
        #pragma unroll
        for (int q = 0; q < 2; q++) {
            int idx = tid * 2 + q;             // 0..511
            int row = idx >> 2, k4 = idx & 3;
            float4 v = *(const float4*)&A[(size_t)(bm + row) * K + k0 + k4 * 4];
            As[k4*4+0][row] = v.x; As[k4*4+1][row] = v.y;
            As[k4*4+2][row] = v.z; As[k4*4+3][row] = v.w;
        }
        {
            int kr = tid >> 4, c4 = tid & 15;  // 16 k-rows x 16 col-chunks
            *(float4*)&Bs[kr][c4*4] = *(const float4*)&B[(size_t)(k0 + kr) * N + bn + c4 * 4];
        }
        __syncthreads();
        #pragma unroll
        for (int kk = 0; kk < BKK; kk++) {
            float4 a0 = *(float4*)&As[kk][ty*8];
            float4 a1 = *(float4*)&As[kk][ty*8+4];
            float4 bv = *(float4*)&Bs[kk][tx*4];
            float av[8] = {a0.x,a0.y,a0.z,a0.w,a1.x,a1.y,a1.z,a1.w};
            float bw[4] = {bv.x,bv.y,bv.z,bv.w};
            #pragma unroll
            for (int i = 0; i < 8; i++)
                #pragma unroll
                for (int j = 0; j < 4; j++)
                    acc[i][j] = fmaf(av[i], bw[j], acc[i][j]);
        }
        __syncthreads();
    }

    int col = bn + tx * 4;
    float4 bi = make_float4(0.f, 0.f, 0.f, 0.f);
    if (EPI != 4) bi = *(const float4*)&bias[col];

    #pragma unroll
    for (int i = 0; i < 8; i++) {
        int row = bm + ty * 8 + i;
        float4 v;
        v.x = acc[i][0] + bi.x;
        v.y = acc[i][1] + bi.y;
        v.z = acc[i][2] + bi.z;
        v.w = acc[i][3] + bi.w;
        if (EPI == 2) {
            v.x = gelu_exact(v.x); v.y = gelu_exact(v.y);
            v.z = gelu_exact(v.z); v.w = gelu_exact(v.w);
        }
        if (EPI == 1) {
            int wi = row >> 6, n = row & 63;
            int b  = wi / NWIN, wl = wi % NWIN;
            int whi = wl / 12, wwi = wl % 12;
            int h0 = whi * 8 + (n >> 3), w0 = wwi * 8 + (n & 7);
            int h = h0 + shift; if (h >= HH) h -= HH;
            int w = w0 + shift; if (w >= WW) w -= WW;
            int dst = b * LL + h * WW + w;
            float4 r4 = *(const float4*)&res[(size_t)dst * N + col];
            v.x += r4.x; v.y += r4.y; v.z += r4.z; v.w += r4.w;
            *(float4*)&C[(size_t)dst * N + col] = v;
        } else if (EPI == 3) {
            float4 r4 = *(const float4*)&res[(size_t)row * N + col];
            v.x += r4.x; v.y += r4.y; v.z += r4.z; v.w += r4.w;
            *(float4*)&C[(size_t)row * N + col] = v;
        } else {
            *(float4*)&C[(size_t)row * N + col] = v;
        }
    }
}

// ---------------- windowed attention: one block per (window, head) ----------
__global__ __launch_bounds__(64) void attn_kernel(
    const float* __restrict__ qkv, float* __restrict__ out, int shifted)
{
    __shared__ float k_s[NTOK * HD];
    __shared__ float v_s[NTOK * HD];
    __shared__ int   lab_s[NTOK];

    int wi   = blockIdx.x >> 2;
    int head = blockIdx.x & 3;
    int n    = threadIdx.x;                 // 0..63 row within window

    size_t rowbase = (size_t)(wi * NTOK + n) * (3 * CC);
    const float* krow = &qkv[rowbase + CC     + head * HD];
    const float* vrow = &qkv[rowbase + 2 * CC + head * HD];
    #pragma unroll
    for (int i = 0; i < 8; i++) {
        *(float4*)&k_s[n * HD + i * 4] = *(const float4*)&krow[i * 4];
        *(float4*)&v_s[n * HD + i * 4] = *(const float4*)&vrow[i * 4];
    }
    int mylab = 0;
    if (shifted) {
        int wl = wi % NWIN;
        int whi = wl / 12, wwi = wl % 12;
        int h = whi * 8 + (n >> 3), w = wwi * 8 + (n & 7);
        int hr = (h < HH - WS) ? 0 : ((h < HH - 4) ? 1 : 2);
        int wr = (w < WW - WS) ? 0 : ((w < WW - 4) ? 1 : 2);
        mylab = hr * 3 + wr;
        lab_s[n] = mylab;
    }
    float q[HD];
    {
        const float* qrow = &qkv[rowbase + head * HD];
        #pragma unroll
        for (int i = 0; i < 8; i++) {
            float4 t = *(const float4*)&qrow[i * 4];
            q[i*4+0] = t.x * QKSCALE; q[i*4+1] = t.y * QKSCALE;
            q[i*4+2] = t.z * QKSCALE; q[i*4+3] = t.w * QKSCALE;
        }
    }
    __syncthreads();

    float s[NTOK];
    #pragma unroll
    for (int j = 0; j < NTOK; j++) {
        float a = 0.f;
        #pragma unroll
        for (int d = 0; d < HD; d++) a = fmaf(q[d], k_s[j * HD + d], a);
        s[j] = a;
    }
    if (shifted) {
        #pragma unroll
        for (int j = 0; j < NTOK; j++)
            if (lab_s[j] != mylab) s[j] = -1e30f;
    }
    float m = -1e30f;
    #pragma unroll
    for (int j = 0; j < NTOK; j++) m = fmaxf(m, s[j]);
    float sum = 0.f;
    #pragma unroll
    for (int j = 0; j < NTOK; j++) { s[j] = __expf(s[j] - m); sum += s[j]; }
    float inv = 1.f / sum;

    float o[HD];
    #pragma unroll
    for (int d = 0; d < HD; d++) o[d] = 0.f;
    #pragma unroll
    for (int j = 0; j < NTOK; j++) {
        float p = s[j];
        #pragma unroll
        for (int d = 0; d < HD; d++) o[d] = fmaf(p, v_s[j * HD + d], o[d]);
    }
    float* orow = &out[(size_t)(wi * NTOK + n) * CC + head * HD];
    #pragma unroll
    for (int i = 0; i < 8; i++) {
        float4 t;
        t.x = o[i*4+0] * inv; t.y = o[i*4+1] * inv;
        t.z = o[i*4+2] * inv; t.w = o[i*4+3] * inv;
        *(float4*)&orow[i * 4] = t;
    }
}

// ---------------- patch-merge gather + LN(512) -------------------------------
__global__ __launch_bounds__(128) void pm_ln_kernel(
    const float* __restrict__ x, const float* __restrict__ gam,
    const float* __restrict__ bet, float* __restrict__ out)
{
    int lane = threadIdx.x & 31;
    int warp = threadIdx.x >> 5;
    int i = blockIdx.x * 4 + warp;          // 0..18431
    int b = i / 2304, pos = i % 2304;
    int oh = pos / 48, ow = pos % 48;
    int base = b * LL;
    int src[4];
    src[0] = base + (2*oh    ) * WW + 2*ow;
    src[1] = base + (2*oh + 1) * WW + 2*ow;
    src[2] = base + (2*oh    ) * WW + 2*ow + 1;
    src[3] = base + (2*oh + 1) * WW + 2*ow + 1;

    float4 v[4];
    float s1 = 0.f, s2 = 0.f;
    #pragma unroll
    for (int k = 0; k < 4; k++) {
        v[k] = *(const float4*)&x[(size_t)src[k] * CC + lane * 4];
        s1 += v[k].x + v[k].y + v[k].z + v[k].w;
        s2 += v[k].x*v[k].x + v[k].y*v[k].y + v[k].z*v[k].z + v[k].w*v[k].w;
    }
    #pragma unroll
    for (int o = 16; o; o >>= 1) {
        s1 += __shfl_xor_sync(0xffffffffu, s1, o);
        s2 += __shfl_xor_sync(0xffffffffu, s2, o);
    }
    float mean = s1 * (1.f / 512.f);
    float var  = s2 * (1.f / 512.f) - mean * mean;
    float rstd = rsqrtf(var + 1e-5f);
    #pragma unroll
    for (int k = 0; k < 4; k++) {
        int col = k * CC + lane * 4;
        float4 g4 = *(const float4*)&gam[col];
        float4 b4 = *(const float4*)&bet[col];
        float4 o4;
        o4.x = (v[k].x - mean) * rstd * g4.x + b4.x;
        o4.y = (v[k].y - mean) * rstd * g4.y + b4.y;
        o4.z = (v[k].z - mean) * rstd * g4.z + b4.z;
        o4.w = (v[k].w - mean) * rstd * g4.w + b4.w;
        *(float4*)&out[(size_t)i * 512 + col] = o4;
    }
}

// ---------------- host orchestration ----------------------------------------
static void run_block(const float* xin, float* xout, const float* const* p, int shift,
                      float* xw, float* qkv, float* att, float* h)
{
    // p: ln1_g, ln1_b, qkv_w, qkv_b, proj_w, proj_b, ln2_g, ln2_b, fc1_w, fc1_b, fc2_w, fc2_b
    ln_kernel<true><<<ROWS/4, 128>>>(xin, p[0], p[1], xw, shift);
    gemm_kernel<0><<<dim3(ROWS/BM, 384/BN), 256>>>(xw, p[2], p[3], qkv, nullptr, ROWS, 384, CC, 0);
    attn_kernel<<<(ROWS/NTOK)*HEADS, 64>>>(qkv, att, shift > 0 ? 1 : 0);
    gemm_kernel<1><<<dim3(ROWS/BM, CC/BN), 256>>>(att, p[4], p[5], xout, xin, ROWS, CC, CC, shift);
    ln_kernel<false><<<ROWS/4, 128>>>(xout, p[6], p[7], xw, 0);
    gemm_kernel<2><<<dim3(ROWS/BM, 512/BN), 256>>>(xw, p[8], p[9], h, nullptr, ROWS, 512, CC, 0);
    gemm_kernel<3><<<dim3(ROWS/BM, CC/BN), 256>>>(h, p[10], p[11], xout, xout, ROWS, CC, 512, 0);
}

extern "C" void kernel_launch(void* const* d_in, const int* in_sizes, int n_in,
                              void* d_out, int out_size)
{
    (void)in_sizes; (void)n_in;
    const float* x = (const float*)d_in[0];
    const float* pa[12];
    const float* pb[12];
    for (int i = 0; i < 12; i++) pa[i] = (const float*)d_in[1 + i];
    for (int i = 0; i < 12; i++) pb[i] = (const float*)d_in[13 + i];
    const float* mln_g = (const float*)d_in[25];
    const float* mln_b = (const float*)d_in[26];
    const float* red_w = (const float*)d_in[27];
    float* out = (float*)d_out;
    (void)out_size;

    float *xw, *qkv, *att, *xa, *xb, *h;
    cudaGetSymbolAddress((void**)&xw,  g_xw);
    cudaGetSymbolAddress((void**)&qkv, g_qkv);
    cudaGetSymbolAddress((void**)&att, g_att);
    cudaGetSymbolAddress((void**)&xa,  g_xa);
    cudaGetSymbolAddress((void**)&xb,  g_xb);
    cudaGetSymbolAddress((void**)&h,   g_h);

    run_block(x,  xa, pa, 0, xw, qkv, att, h);   // W-MSA block
    run_block(xa, xb, pb, 4, xw, qkv, att, h);   // SW-MSA block (shift = ws/2 = 4)

    // patch merge: gather+LN(512) into att (reused as xc), then GEMM to out
    pm_ln_kernel<<<(ROWS/4)/NTOK * 16, 128>>>(xb, mln_g, mln_b, att); // 4608 blocks
    gemm_kernel<4><<<dim3((ROWS/4)/BM, 256/BN), 256>>>(att, red_w, nullptr, out, nullptr,
                                                       ROWS/4, 256, 512, 0);
}

// round 3
// speedup vs baseline: 2.5518x; 2.5518x over previous
#include <cuda_runtime.h>
#include <cuda_bf16.h>
#include <cstdint>

// Problem constants
#define BATCH 8
#define HH 96
#define WW 96
#define CC 128
#define LL (HH*WW)            // 9216
#define ROWS (BATCH*LL)       // 73728
#define NWIN 144
#define WS 8
#define NTOK 64
#define HEADS 4
#define HD 32
#define QKSCALE 0.17677669529663687f

// ---------------- scratch -----------------
__device__ float g_xw [ (size_t)ROWS*CC ];
__device__ float g_qkv[ (size_t)ROWS*3*CC ];
__device__ float g_att[ (size_t)ROWS*CC ];
__device__ float g_xa [ (size_t)ROWS*CC ];
__device__ float g_xb [ (size_t)ROWS*CC ];
__device__ float g_h  [ (size_t)ROWS*4*CC ];
__device__ float g_wt [ 524288 ];   // transposed weights

__device__ __forceinline__ uint32_t smem_u32(const void* p) {
    uint32_t a;
    asm("{ .reg .u64 t; cvta.to.shared.u64 t, %1; cvt.u32.u64 %0, t; }" : "=r"(a) : "l"(p));
    return a;
}
__device__ __forceinline__ uint32_t f2tf32(float x) {
    uint32_t u;
    asm("cvt.rna.tf32.f32 %0, %1;" : "=r"(u) : "f"(x));
    return u;
}
__device__ __forceinline__ float gelu_exact(float x) {
    return 0.5f * x * (1.f + erff(x * 0.70710678118654752f));
}

// ---------------- LayerNorm (+ optional gather) -----------------------------
template<bool GATHER>
__global__ __launch_bounds__(128) void ln_kernel(
    const float* __restrict__ x, const float* __restrict__ gam,
    const float* __restrict__ bet, float* __restrict__ out, int shift)
{
    int lane = threadIdx.x & 31;
    int warp = threadIdx.x >> 5;
    int r = blockIdx.x * 4 + warp;
    const float* src;
    if (GATHER) {
        int wi = r >> 6, n = r & 63;
        int b  = wi / NWIN, wl = wi % NWIN;
        int whi = wl / 12, wwi = wl % 12;
        int h0 = whi * 8 + (n >> 3), w0 = wwi * 8 + (n & 7);
        int hs = h0 + shift; if (hs >= HH) hs -= HH;
        int ws_ = w0 + shift; if (ws_ >= WW) ws_ -= WW;
        src = &x[(size_t)(b * LL + hs * WW + ws_) * CC];
    } else {
        src = &x[(size_t)r * CC];
    }
    float4 v = *(const float4*)&src[lane * 4];
    float s1 = v.x + v.y + v.z + v.w;
    float s2 = v.x*v.x + v.y*v.y + v.z*v.z + v.w*v.w;
    #pragma unroll
    for (int o = 16; o; o >>= 1) {
        s1 += __shfl_xor_sync(0xffffffffu, s1, o);
        s2 += __shfl_xor_sync(0xffffffffu, s2, o);
    }
    float mean = s1 * (1.f / CC);
    float var  = s2 * (1.f / CC) - mean * mean;
    float rstd = rsqrtf(var + 1e-5f);
    float4 g4 = *(const float4*)&gam[lane * 4];
    float4 b4 = *(const float4*)&bet[lane * 4];
    float4 o4;
    o4.x = (v.x - mean) * rstd * g4.x + b4.x;
    o4.y = (v.y - mean) * rstd * g4.y + b4.y;
    o4.z = (v.z - mean) * rstd * g4.z + b4.z;
    o4.w = (v.w - mean) * rstd * g4.w + b4.w;
    *(float4*)&out[(size_t)r * CC + lane * 4] = o4;
}

// ---------------- weight transpose: src[K][N] -> dst[N][K] ------------------
__global__ __launch_bounds__(256) void transpose_kernel(
    const float* __restrict__ src, float* __restrict__ dst, int K, int N)
{
    __shared__ float t[32][33];
    int k0 = blockIdx.x * 32, n0 = blockIdx.y * 32;
    int x = threadIdx.x & 31, y = threadIdx.x >> 5;
    #pragma unroll
    for (int i = 0; i < 32; i += 8)
        t[y + i][x] = src[(size_t)(k0 + y + i) * N + n0 + x];
    __syncthreads();
    #pragma unroll
    for (int i = 0; i < 32; i += 8)
        dst[(size_t)(n0 + y + i) * K + k0 + x] = t[x][y + i];
}

// ---------------- tf32 mma.sync GEMM --------------------------------------
// C[M,N] = A[M,K] @ Bt[N,K]^T, 128x128x32 CTA tile, 8 warps (32x64 warp tile)
// EPI 0: +bias | 1: +bias, window-reverse scatter + residual | 2: +bias, GELU
// EPI 3: +bias, += residual | 4: plain
#define SM_STRIDE 36                       // 32 floats + 4 pad
#define SM_TILE   (128*SM_STRIDE)          // floats per matrix buffer
#define GM_SMEM   (4*SM_TILE*4)            // bytes: A0,B0,A1,B1 = 73728

__device__ __forceinline__ void copy_chunk(
    const float* __restrict__ A, const float* __restrict__ B,
    int bm, int bn, int K, int k0, float* sA, float* sB, int tid)
{
    uint32_t a_s = smem_u32(sA), b_s = smem_u32(sB);
    #pragma unroll
    for (int i = 0; i < 4; i++) {
        int idx = tid + i * 256;
        int row = idx >> 3, q = idx & 7;
        const float* ga = &A[(size_t)(bm + row) * K + k0 + q * 4];
        const float* gb = &B[(size_t)(bn + row) * K + k0 + q * 4];
        uint32_t so = (row * SM_STRIDE + q * 4) * 4;
        asm volatile("cp.async.cg.shared.global [%0],[%1],16;" :: "r"(a_s + so), "l"(ga));
        asm volatile("cp.async.cg.shared.global [%0],[%1],16;" :: "r"(b_s + so), "l"(gb));
    }
    asm volatile("cp.async.commit_group;" ::: "memory");
}

template<int EPI>
__global__ __launch_bounds__(256)
void gemm_mma(const float* __restrict__ A, const float* __restrict__ B,
              const float* __restrict__ bias, float* __restrict__ C,
              const float* __restrict__ res, int M, int N, int K, int shift)
{
    extern __shared__ float sm[];
    float* bufA[2] = { sm,              sm + 2*SM_TILE };
    float* bufB[2] = { sm + SM_TILE,    sm + 3*SM_TILE };
    int tid = threadIdx.x, lane = tid & 31, wid = tid >> 5;
    int g = lane >> 2, kq = lane & 3;
    int warpM = wid & 3, warpN = wid >> 2;
    int bm = blockIdx.x * 128, bn = blockIdx.y * 128;

    float acc[2][8][4];
    #pragma unroll
    for (int i = 0; i < 2; i++)
        #pragma unroll
        for (int j = 0; j < 8; j++)
            #pragma unroll
            for (int q = 0; q < 4; q++) acc[i][j][q] = 0.f;

    int nc = K >> 5;
    copy_chunk(A, B, bm, bn, K, 0, bufA[0], bufB[0], tid);

    for (int c = 0; c < nc; c++) {
        if (c + 1 < nc) {
            copy_chunk(A, B, bm, bn, K, (c + 1) << 5, bufA[(c+1)&1], bufB[(c+1)&1], tid);
            asm volatile("cp.async.wait_group 1;" ::: "memory");
        } else {
            asm volatile("cp.async.wait_group 0;" ::: "memory");
        }
        __syncthreads();

        const float* Af = bufA[c&1] + (warpM * 32 + g) * SM_STRIDE;
        const float* Bf = bufB[c&1] + (warpN * 64 + g) * SM_STRIDE;
        #pragma unroll
        for (int ks = 0; ks < 4; ks++) {
            int kb = ks * 8 + kq;
            uint32_t a[2][4], b[8][2];
            #pragma unroll
            for (int i = 0; i < 2; i++) {
                a[i][0] = f2tf32(Af[i*16*SM_STRIDE + kb]);
                a[i][1] = f2tf32(Af[i*16*SM_STRIDE + 8*SM_STRIDE + kb]);
                a[i][2] = f2tf32(Af[i*16*SM_STRIDE + kb + 4]);
                a[i][3] = f2tf32(Af[i*16*SM_STRIDE + 8*SM_STRIDE + kb + 4]);
            }
            #pragma unroll
            for (int j = 0; j < 8; j++) {
                b[j][0] = f2tf32(Bf[j*8*SM_STRIDE + kb]);
                b[j][1] = f2tf32(Bf[j*8*SM_STRIDE + kb + 4]);
            }
            #pragma unroll
            for (int i = 0; i < 2; i++)
                #pragma unroll
                for (int j = 0; j < 8; j++)
                    asm volatile(
                        "mma.sync.aligned.m16n8k8.row.col.f32.tf32.tf32.f32 "
                        "{%0,%1,%2,%3},{%4,%5,%6,%7},{%8,%9},{%0,%1,%2,%3};"
                        : "+f"(acc[i][j][0]), "+f"(acc[i][j][1]),
                          "+f"(acc[i][j][2]), "+f"(acc[i][j][3])
                        : "r"(a[i][0]), "r"(a[i][1]), "r"(a[i][2]), "r"(a[i][3]),
                          "r"(b[j][0]), "r"(b[j][1]));
        }
        __syncthreads();
    }

    // epilogue: direct float2 stores per (row, col-pair)
    #pragma unroll
    for (int i = 0; i < 2; i++) {
        #pragma unroll
        for (int rr = 0; rr < 2; rr++) {
            int gr = bm + warpM * 32 + i * 16 + g + rr * 8;
            int dst = gr;
            if (EPI == 1) {
                int wi = gr >> 6, n = gr & 63;
                int b  = wi / NWIN, wl = wi % NWIN;
                int whi = wl / 12, wwi = wl % 12;
                int h0 = whi * 8 + (n >> 3), w0 = wwi * 8 + (n & 7);
                int h = h0 + shift; if (h >= HH) h -= HH;
                int w = w0 + shift; if (w >= WW) w -= WW;
                dst = b * LL + h * WW + w;
            }
            #pragma unroll
            for (int j = 0; j < 8; j++) {
                int col = bn + warpN * 64 + j * 8 + 2 * kq;
                float vx = acc[i][j][rr*2+0];
                float vy = acc[i][j][rr*2+1];
                if (EPI != 4) {
                    vx += __ldg(&bias[col]);
                    vy += __ldg(&bias[col+1]);
                }
                if (EPI == 2) { vx = gelu_exact(vx); vy = gelu_exact(vy); }
                if (EPI == 1 || EPI == 3) {
                    float2 r2 = *(const float2*)&res[(size_t)dst * N + col];
                    vx += r2.x; vy += r2.y;
                }
                float2 o2 = make_float2(vx, vy);
                *(float2*)&C[(size_t)dst * N + col] = o2;
            }
        }
    }
}

// ---------------- windowed attention ---------------------------------------
__global__ __launch_bounds__(64) void attn_kernel(
    const float* __restrict__ qkv, float* __restrict__ out, int shifted)
{
    __shared__ float k_s[NTOK * HD];
    __shared__ float v_s[NTOK * HD];
    __shared__ int   lab_s[NTOK];
    int wi = blockIdx.x >> 2, head = blockIdx.x & 3, n = threadIdx.x;
    size_t rowbase = (size_t)(wi * NTOK + n) * (3 * CC);
    const float* krow = &qkv[rowbase + CC     + head * HD];
    const float* vrow = &qkv[rowbase + 2 * CC + head * HD];
    #pragma unroll
    for (int i = 0; i < 8; i++) {
        *(float4*)&k_s[n * HD + i * 4] = *(const float4*)&krow[i * 4];
        *(float4*)&v_s[n * HD + i * 4] = *(const float4*)&vrow[i * 4];
    }
    int mylab = 0;
    if (shifted) {
        int wl = wi % NWIN;
        int whi = wl / 12, wwi = wl % 12;
        int h = whi * 8 + (n >> 3), w = wwi * 8 + (n & 7);
        int hr = (h < HH - WS) ? 0 : ((h < HH - 4) ? 1 : 2);
        int wr = (w < WW - WS) ? 0 : ((w < WW - 4) ? 1 : 2);
        mylab = hr * 3 + wr;
        lab_s[n] = mylab;
    }
    float q[HD];
    {
        const float* qrow = &qkv[rowbase + head * HD];
        #pragma unroll
        for (int i = 0; i < 8; i++) {
            float4 t = *(const float4*)&qrow[i * 4];
            q[i*4+0] = t.x * QKSCALE; q[i*4+1] = t.y * QKSCALE;
            q[i*4+2] = t.z * QKSCALE; q[i*4+3] = t.w * QKSCALE;
        }
    }
    __syncthreads();
    float s[NTOK];
    #pragma unroll
    for (int j = 0; j < NTOK; j++) {
        float a = 0.f;
        #pragma unroll
        for (int d = 0; d < HD; d++) a = fmaf(q[d], k_s[j * HD + d], a);
        s[j] = a;
    }
    if (shifted) {
        #pragma unroll
        for (int j = 0; j < NTOK; j++)
            if (lab_s[j] != mylab) s[j] = -1e30f;
    }
    float m = -1e30f;
    #pragma unroll
    for (int j = 0; j < NTOK; j++) m = fmaxf(m, s[j]);
    float sum = 0.f;
    #pragma unroll
    for (int j = 0; j < NTOK; j++) { s[j] = __expf(s[j] - m); sum += s[j]; }
    float inv = 1.f / sum;
    float o[HD];
    #pragma unroll
    for (int d = 0; d < HD; d++) o[d] = 0.f;
    #pragma unroll
    for (int j = 0; j < NTOK; j++) {
        float p = s[j];
        #pragma unroll
        for (int d = 0; d < HD; d++) o[d] = fmaf(p, v_s[j * HD + d], o[d]);
    }
    float* orow = &out[(size_t)(wi * NTOK + n) * CC + head * HD];
    #pragma unroll
    for (int i = 0; i < 8; i++) {
        float4 t;
        t.x = o[i*4+0] * inv; t.y = o[i*4+1] * inv;
        t.z = o[i*4+2] * inv; t.w = o[i*4+3] * inv;
        *(float4*)&orow[i * 4] = t;
    }
}

// ---------------- patch-merge gather + LN(512) ------------------------------
__global__ __launch_bounds__(128) void pm_ln_kernel(
    const float* __restrict__ x, const float* __restrict__ gam,
    const float* __restrict__ bet, float* __restrict__ out)
{
    int lane = threadIdx.x & 31;
    int warp = threadIdx.x >> 5;
    int i = blockIdx.x * 4 + warp;
    int b = i / 2304, pos = i % 2304;
    int oh = pos / 48, ow = pos % 48;
    int base = b * LL;
    int src[4];
    src[0] = base + (2*oh    ) * WW + 2*ow;
    src[1] = base + (2*oh + 1) * WW + 2*ow;
    src[2] = base + (2*oh    ) * WW + 2*ow + 1;
    src[3] = base + (2*oh + 1) * WW + 2*ow + 1;
    float4 v[4];
    float s1 = 0.f, s2 = 0.f;
    #pragma unroll
    for (int k = 0; k < 4; k++) {
        v[k] = *(const float4*)&x[(size_t)src[k] * CC + lane * 4];
        s1 += v[k].x + v[k].y + v[k].z + v[k].w;
        s2 += v[k].x*v[k].x + v[k].y*v[k].y + v[k].z*v[k].z + v[k].w*v[k].w;
    }
    #pragma unroll
    for (int o = 16; o; o >>= 1) {
        s1 += __shfl_xor_sync(0xffffffffu, s1, o);
        s2 += __shfl_xor_sync(0xffffffffu, s2, o);
    }
    float mean = s1 * (1.f / 512.f);
    float var  = s2 * (1.f / 512.f) - mean * mean;
    float rstd = rsqrtf(var + 1e-5f);
    #pragma unroll
    for (int k = 0; k < 4; k++) {
        int col = k * CC + lane * 4;
        float4 g4 = *(const float4*)&gam[col];
        float4 b4 = *(const float4*)&bet[col];
        float4 o4;
        o4.x = (v[k].x - mean) * rstd * g4.x + b4.x;
        o4.y = (v[k].y - mean) * rstd * g4.y + b4.y;
        o4.z = (v[k].z - mean) * rstd * g4.z + b4.z;
        o4.w = (v[k].w - mean) * rstd * g4.w + b4.w;
        *(float4*)&out[(size_t)i * 512 + col] = o4;
    }
}

// ---------------- host orchestration ----------------------------------------
static void run_block(const float* xin, float* xout, const float* const* p, int shift,
                      const float* qkv_t, const float* proj_t, const float* fc1_t, const float* fc2_t,
                      float* xw, float* qkv, float* att, float* h)
{
    ln_kernel<true><<<ROWS/4, 128>>>(xin, p[0], p[1], xw, shift);
    gemm_mma<0><<<dim3(ROWS/128, 3), 256, GM_SMEM>>>(xw, qkv_t, p[3], qkv, nullptr, ROWS, 384, CC, 0);
    attn_kernel<<<(ROWS/NTOK)*HEADS, 64>>>(qkv, att, shift > 0 ? 1 : 0);
    gemm_mma<1><<<dim3(ROWS/128, 1), 256, GM_SMEM>>>(att, proj_t, p[5], xout, xin, ROWS, CC, CC, shift);
    ln_kernel<false><<<ROWS/4, 128>>>(xout, p[6], p[7], xw, 0);
    gemm_mma<2><<<dim3(ROWS/128, 4), 256, GM_SMEM>>>(xw, fc1_t, p[9], h, nullptr, ROWS, 512, CC, 0);
    gemm_mma<3><<<dim3(ROWS/128, 1), 256, GM_SMEM>>>(h, fc2_t, p[11], xout, xout, ROWS, CC, 512, 0);
}

extern "C" void kernel_launch(void* const* d_in, const int* in_sizes, int n_in,
                              void* d_out, int out_size)
{
    (void)in_sizes; (void)n_in; (void)out_size;
    const float* x = (const float*)d_in[0];
    const float* pa[12];
    const float* pb[12];
    for (int i = 0; i < 12; i++) pa[i] = (const float*)d_in[1 + i];
    for (int i = 0; i < 12; i++) pb[i] = (const float*)d_in[13 + i];
    const float* mln_g = (const float*)d_in[25];
    const float* mln_b = (const float*)d_in[26];
    const float* red_w = (const float*)d_in[27];
    float* out = (float*)d_out;

    float *xw, *qkv, *att, *xa, *xb, *h, *wt;
    cudaGetSymbolAddress((void**)&xw,  g_xw);
    cudaGetSymbolAddress((void**)&qkv, g_qkv);
    cudaGetSymbolAddress((void**)&att, g_att);
    cudaGetSymbolAddress((void**)&xa,  g_xa);
    cudaGetSymbolAddress((void**)&xb,  g_xb);
    cudaGetSymbolAddress((void**)&h,   g_h);
    cudaGetSymbolAddress((void**)&wt,  g_wt);

    static bool attr_done = false;
    if (!attr_done) {
        cudaFuncSetAttribute(gemm_mma<0>, cudaFuncAttributeMaxDynamicSharedMemorySize, GM_SMEM);
        cudaFuncSetAttribute(gemm_mma<1>, cudaFuncAttributeMaxDynamicSharedMemorySize, GM_SMEM);
        cudaFuncSetAttribute(gemm_mma<2>, cudaFuncAttributeMaxDynamicSharedMemorySize, GM_SMEM);
        cudaFuncSetAttribute(gemm_mma<3>, cudaFuncAttributeMaxDynamicSharedMemorySize, GM_SMEM);
        cudaFuncSetAttribute(gemm_mma<4>, cudaFuncAttributeMaxDynamicSharedMemorySize, GM_SMEM);
        attr_done = true;
    }

    float* a_qkv_t  = wt;            // 384*128
    float* a_proj_t = wt + 49152;    // 128*128
    float* a_fc1_t  = wt + 65536;    // 512*128
    float* a_fc2_t  = wt + 131072;   // 128*512
    float* b_qkv_t  = wt + 196608;
    float* b_proj_t = wt + 245760;
    float* b_fc1_t  = wt + 262144;
    float* b_fc2_t  = wt + 327680;
    float* red_t    = wt + 393216;   // 256*512

    transpose_kernel<<<dim3(4, 12), 256>>>(pa[2],  a_qkv_t,  128, 384);
    transpose_kernel<<<dim3(4, 4),  256>>>(pa[4],  a_proj_t, 128, 128);
    transpose_kernel<<<dim3(4, 16), 256>>>(pa[8],  a_fc1_t,  128, 512);
    transpose_kernel<<<dim3(16, 4), 256>>>(pa[10], a_fc2_t,  512, 128);
    transpose_kernel<<<dim3(4, 12), 256>>>(pb[2],  b_qkv_t,  128, 384);
    transpose_kernel<<<dim3(4, 4),  256>>>(pb[4],  b_proj_t, 128, 128);
    transpose_kernel<<<dim3(4, 16), 256>>>(pb[8],  b_fc1_t,  128, 512);
    transpose_kernel<<<dim3(16, 4), 256>>>(pb[10], b_fc2_t,  512, 128);
    transpose_kernel<<<dim3(16, 8), 256>>>(red_w,  red_t,    512, 256);

    run_block(x,  xa, pa, 0, a_qkv_t, a_proj_t, a_fc1_t, a_fc2_t, xw, qkv, att, h);
    run_block(xa, xb, pb, 4, b_qkv_t, b_proj_t, b_fc1_t, b_fc2_t, xw, qkv, att, h);

    pm_ln_kernel<<<(ROWS/4)/NTOK * 16, 128>>>(xb, mln_g, mln_b, att);
    gemm_mma<4><<<dim3((ROWS/4)/128, 2), 256, GM_SMEM>>>(att, red_t, nullptr, out, nullptr,
                                                         ROWS/4, 256, 512, 0);
}

// round 4
// speedup vs baseline: 3.9787x; 1.5592x over previous
#include <cuda_runtime.h>
#include <cuda_fp16.h>
#include <cstdint>

// Problem constants
#define BATCH 8
#define HH 96
#define WW 96
#define CC 128
#define LL (HH*WW)            // 9216
#define ROWS (BATCH*LL)       // 73728
#define NWIN 144
#define WS 8
#define NTOK 64
#define HEADS 4
#define HD 32
#define QKSCALE 0.17677669529663687f

// ---------------- scratch -----------------
__device__ __half g_xw [ (size_t)ROWS*CC ];     // LN out (GEMM A)
__device__ __half g_qkv[ (size_t)ROWS*3*CC ];   // qkv (half)
__device__ __half g_att[ (size_t)ROWS*CC ];     // attn out / pm-LN out (GEMM A)
__device__ float  g_xa [ (size_t)ROWS*CC ];     // residual fp32
__device__ float  g_xb [ (size_t)ROWS*CC ];
__device__ __half g_h  [ (size_t)ROWS*4*CC ];   // MLP hidden (half)
__device__ __half g_wt [ 524288 ];              // transposed weights (half)

__device__ __forceinline__ uint32_t smem_u32(const void* p) {
    uint32_t a;
    asm("{ .reg .u64 t; cvta.to.shared.u64 t, %1; cvt.u32.u64 %0, t; }" : "=r"(a) : "l"(p));
    return a;
}
__device__ __forceinline__ float gelu_exact(float x) {
    return 0.5f * x * (1.f + erff(x * 0.70710678118654752f));
}
__device__ __forceinline__ uint2 f4_to_h4(float4 v) {
    union { uint2 u; __half2 h[2]; } cv;
    cv.h[0] = __floats2half2_rn(v.x, v.y);
    cv.h[1] = __floats2half2_rn(v.z, v.w);
    return cv.u;
}

#define LDSM4(r, addr) \
    asm volatile("ldmatrix.sync.aligned.m8n8.x4.shared.b16 {%0,%1,%2,%3},[%4];" \
        : "=r"((r)[0]), "=r"((r)[1]), "=r"((r)[2]), "=r"((r)[3]) : "r"(addr))

// ---------------- LayerNorm (+ optional gather), half output ----------------
template<bool GATHER>
__global__ __launch_bounds__(128) void ln_kernel(
    const float* __restrict__ x, const float* __restrict__ gam,
    const float* __restrict__ bet, __half* __restrict__ out, int shift)
{
    int lane = threadIdx.x & 31;
    int warp = threadIdx.x >> 5;
    int r = blockIdx.x * 4 + warp;
    const float* src;
    if (GATHER) {
        int wi = r >> 6, n = r & 63;
        int b  = wi / NWIN, wl = wi % NWIN;
        int whi = wl / 12, wwi = wl % 12;
        int h0 = whi * 8 + (n >> 3), w0 = wwi * 8 + (n & 7);
        int hs = h0 + shift; if (hs >= HH) hs -= HH;
        int ws_ = w0 + shift; if (ws_ >= WW) ws_ -= WW;
        src = &x[(size_t)(b * LL + hs * WW + ws_) * CC];
    } else {
        src = &x[(size_t)r * CC];
    }
    float4 v = *(const float4*)&src[lane * 4];
    float s1 = v.x + v.y + v.z + v.w;
    float s2 = v.x*v.x + v.y*v.y + v.z*v.z + v.w*v.w;
    #pragma unroll
    for (int o = 16; o; o >>= 1) {
        s1 += __shfl_xor_sync(0xffffffffu, s1, o);
        s2 += __shfl_xor_sync(0xffffffffu, s2, o);
    }
    float mean = s1 * (1.f / CC);
    float var  = s2 * (1.f / CC) - mean * mean;
    float rstd = rsqrtf(var + 1e-5f);
    float4 g4 = *(const float4*)&gam[lane * 4];
    float4 b4 = *(const float4*)&bet[lane * 4];
    float4 o4;
    o4.x = (v.x - mean) * rstd * g4.x + b4.x;
    o4.y = (v.y - mean) * rstd * g4.y + b4.y;
    o4.z = (v.z - mean) * rstd * g4.z + b4.z;
    o4.w = (v.w - mean) * rstd * g4.w + b4.w;
    *(uint2*)&out[(size_t)r * CC + lane * 4] = f4_to_h4(o4);
}

// ---------------- weight transpose: src[K][N] fp32 -> dst[N][K] half --------
__global__ __launch_bounds__(256) void transpose_kernel(
    const float* __restrict__ src, __half* __restrict__ dst, int K, int N)
{
    __shared__ float t[32][33];
    int k0 = blockIdx.x * 32, n0 = blockIdx.y * 32;
    int x = threadIdx.x & 31, y = threadIdx.x >> 5;
    #pragma unroll
    for (int i = 0; i < 32; i += 8)
        t[y + i][x] = src[(size_t)(k0 + y + i) * N + n0 + x];
    __syncthreads();
    #pragma unroll
    for (int i = 0; i < 32; i += 8)
        dst[(size_t)(n0 + y + i) * K + k0 + x] = __float2half_rn(t[x][y + i]);
}

// ---------------- fp16 mma.sync GEMM (m16n8k16) ------------------------------
// C[M,N] = A[M,K] @ Bt[N,K]^T.  128x128x32 CTA tile, 8 warps (32x64 warp tile).
// EPI 0: +bias | 1: +bias, window-reverse scatter + residual | 2: +bias, GELU
// EPI 3: +bias, += residual | 4: plain
#define AS_STRIDE 40                       // halves per smem row (32 + 8 pad)
#define TILE_H   (128*AS_STRIDE)           // halves per buffer
#define GM_SMEM  (4*TILE_H*2)              // bytes = 40960 (< 48KB, no opt-in)

__device__ __forceinline__ void copy_chunk(
    const __half* __restrict__ A, const __half* __restrict__ B,
    int bm, int bn, int K, int k0, __half* sA, __half* sB, int tid)
{
    uint32_t a_s = smem_u32(sA), b_s = smem_u32(sB);
    #pragma unroll
    for (int i = 0; i < 2; i++) {
        int idx = tid + i * 256;           // 0..511
        int row = idx >> 2, q = idx & 3;   // 4 x 16B per 64B row-chunk
        const __half* ga = &A[(size_t)(bm + row) * K + k0 + q * 8];
        const __half* gb = &B[(size_t)(bn + row) * K + k0 + q * 8];
        uint32_t so = (row * AS_STRIDE + q * 8) * 2;
        asm volatile("cp.async.cg.shared.global [%0],[%1],16;" :: "r"(a_s + so), "l"(ga));
        asm volatile("cp.async.cg.shared.global [%0],[%1],16;" :: "r"(b_s + so), "l"(gb));
    }
    asm volatile("cp.async.commit_group;" ::: "memory");
}

template<int EPI, typename OT>
__global__ __launch_bounds__(256)
void gemm_mma(const __half* __restrict__ A, const __half* __restrict__ B,
              const float* __restrict__ bias, OT* __restrict__ C,
              const float* __restrict__ res, int M, int N, int K, int shift)
{
    extern __shared__ __half smh[];
    __half* bufA[2] = { smh,          smh + 2*TILE_H };
    __half* bufB[2] = { smh + TILE_H, smh + 3*TILE_H };
    int tid = threadIdx.x, lane = tid & 31, wid = tid >> 5;
    int g = lane >> 2, kq = lane & 3;
    int warpM = wid & 3, warpN = wid >> 2;
    int bm = blockIdx.x * 128, bn = blockIdx.y * 128;

    float acc[2][8][4];
    #pragma unroll
    for (int i = 0; i < 2; i++)
        #pragma unroll
        for (int j = 0; j < 8; j++)
            #pragma unroll
            for (int q = 0; q < 4; q++) acc[i][j][q] = 0.f;

    int nc = K >> 5;
    copy_chunk(A, B, bm, bn, K, 0, bufA[0], bufB[0], tid);

    // per-lane ldmatrix address components (byte offsets within buffer)
    uint32_t a_off = (((warpM * 32 + (lane & 15)) * AS_STRIDE) + ((lane >> 4) << 3)) * 2;
    uint32_t b_off = (((warpN * 64 + (lane & 7) + (((lane >> 4) & 1) << 3)) * AS_STRIDE)
                     + (((lane >> 3) & 1) << 3)) * 2;

    for (int c = 0; c < nc; c++) {
        if (c + 1 < nc) {
            copy_chunk(A, B, bm, bn, K, (c + 1) << 5, bufA[(c+1)&1], bufB[(c+1)&1], tid);
            asm volatile("cp.async.wait_group 1;" ::: "memory");
        } else {
            asm volatile("cp.async.wait_group 0;" ::: "memory");
        }
        __syncthreads();

        uint32_t ab = smem_u32(bufA[c&1]) + a_off;
        uint32_t bb = smem_u32(bufB[c&1]) + b_off;
        #pragma unroll
        for (int ks = 0; ks < 2; ks++) {
            uint32_t a[2][4], b[4][4];
            LDSM4(a[0], ab + ks * 32);
            LDSM4(a[1], ab + 16 * AS_STRIDE * 2 + ks * 32);
            #pragma unroll
            for (int j16 = 0; j16 < 4; j16++)
                LDSM4(b[j16], bb + j16 * 16 * AS_STRIDE * 2 + ks * 32);
            #pragma unroll
            for (int i = 0; i < 2; i++)
                #pragma unroll
                for (int j = 0; j < 8; j++) {
                    uint32_t b0 = b[j >> 1][(j & 1) * 2];
                    uint32_t b1 = b[j >> 1][(j & 1) * 2 + 1];
                    asm volatile(
                        "mma.sync.aligned.m16n8k16.row.col.f32.f16.f16.f32 "
                        "{%0,%1,%2,%3},{%4,%5,%6,%7},{%8,%9},{%0,%1,%2,%3};"
                        : "+f"(acc[i][j][0]), "+f"(acc[i][j][1]),
                          "+f"(acc[i][j][2]), "+f"(acc[i][j][3])
                        : "r"(a[i][0]), "r"(a[i][1]), "r"(a[i][2]), "r"(a[i][3]),
                          "r"(b0), "r"(b1));
                }
        }
        __syncthreads();
    }

    // epilogue: fp32 math, per-(row, col-pair) stores
    #pragma unroll
    for (int i = 0; i < 2; i++) {
        #pragma unroll
        for (int rr = 0; rr < 2; rr++) {
            int gr = bm + warpM * 32 + i * 16 + g + rr * 8;
            int dst = gr;
            if (EPI == 1) {
                int wi = gr >> 6, n = gr & 63;
                int b  = wi / NWIN, wl = wi % NWIN;
                int whi = wl / 12, wwi = wl % 12;
                int h0 = whi * 8 + (n >> 3), w0 = wwi * 8 + (n & 7);
                int h = h0 + shift; if (h >= HH) h -= HH;
                int w = w0 + shift; if (w >= WW) w -= WW;
                dst = b * LL + h * WW + w;
            }
            #pragma unroll
            for (int j = 0; j < 8; j++) {
                int col = bn + warpN * 64 + j * 8 + 2 * kq;
                float vx = acc[i][j][rr*2+0];
                float vy = acc[i][j][rr*2+1];
                if (EPI != 4) {
                    vx += __ldg(&bias[col]);
                    vy += __ldg(&bias[col+1]);
                }
                if (EPI == 2) { vx = gelu_exact(vx); vy = gelu_exact(vy); }
                if (EPI == 1 || EPI == 3) {
                    float2 r2 = *(const float2*)&res[(size_t)dst * N + col];
                    vx += r2.x; vy += r2.y;
                }
                if (sizeof(OT) == 2) {
                    *(__half2*)&((__half*)C)[(size_t)dst * N + col] = __floats2half2_rn(vx, vy);
                } else {
                    *(float2*)&((float*)C)[(size_t)dst * N + col] = make_float2(vx, vy);
                }
            }
        }
    }
}

// ---------------- windowed attention (half in/out, fp32 compute) ------------
__global__ __launch_bounds__(64) void attn_kernel(
    const __half* __restrict__ qkv, __half* __restrict__ out, int shifted)
{
    __shared__ float k_s[NTOK * HD];
    __shared__ float v_s[NTOK * HD];
    __shared__ int   lab_s[NTOK];
    int wi = blockIdx.x >> 2, head = blockIdx.x & 3, n = threadIdx.x;
    size_t rowbase = (size_t)(wi * NTOK + n) * (3 * CC);
    const __half* krow = &qkv[rowbase + CC     + head * HD];
    const __half* vrow = &qkv[rowbase + 2 * CC + head * HD];
    #pragma unroll
    for (int i = 0; i < 4; i++) {
        union { uint4 u; __half2 h[4]; } ck, cv2;
        ck.u  = *(const uint4*)&krow[i * 8];
        cv2.u = *(const uint4*)&vrow[i * 8];
        #pragma unroll
        for (int p = 0; p < 4; p++) {
            float2 fk = __half22float2(ck.h[p]);
            float2 fv = __half22float2(cv2.h[p]);
            k_s[n * HD + i*8 + p*2]     = fk.x;
            k_s[n * HD + i*8 + p*2 + 1] = fk.y;
            v_s[n * HD + i*8 + p*2]     = fv.x;
            v_s[n * HD + i*8 + p*2 + 1] = fv.y;
        }
    }
    int mylab = 0;
    if (shifted) {
        int wl = wi % NWIN;
        int whi = wl / 12, wwi = wl % 12;
        int h = whi * 8 + (n >> 3), w = wwi * 8 + (n & 7);
        int hr = (h < HH - WS) ? 0 : ((h < HH - 4) ? 1 : 2);
        int wr = (w < WW - WS) ? 0 : ((w < WW - 4) ? 1 : 2);
        mylab = hr * 3 + wr;
        lab_s[n] = mylab;
    }
    float q[HD];
    {
        const __half* qrow = &qkv[rowbase + head * HD];
        #pragma unroll
        for (int i = 0; i < 4; i++) {
            union { uint4 u; __half2 h[4]; } cq;
            cq.u = *(const uint4*)&qrow[i * 8];
            #pragma unroll
            for (int p = 0; p < 4; p++) {
                float2 f = __half22float2(cq.h[p]);
                q[i*8 + p*2]     = f.x * QKSCALE;
                q[i*8 + p*2 + 1] = f.y * QKSCALE;
            }
        }
    }
    __syncthreads();
    float s[NTOK];
    #pragma unroll
    for (int j = 0; j < NTOK; j++) {
        float a = 0.f;
        #pragma unroll
        for (int d = 0; d < HD; d++) a = fmaf(q[d], k_s[j * HD + d], a);
        s[j] = a;
    }
    if (shifted) {
        #pragma unroll
        for (int j = 0; j < NTOK; j++)
            if (lab_s[j] != mylab) s[j] = -1e30f;
    }
    float m = -1e30f;
    #pragma unroll
    for (int j = 0; j < NTOK; j++) m = fmaxf(m, s[j]);
    float sum = 0.f;
    #pragma unroll
    for (int j = 0; j < NTOK; j++) { s[j] = __expf(s[j] - m); sum += s[j]; }
    float inv = 1.f / sum;
    float o[HD];
    #pragma unroll
    for (int d = 0; d < HD; d++) o[d] = 0.f;
    #pragma unroll
    for (int j = 0; j < NTOK; j++) {
        float p = s[j];
        #pragma unroll
        for (int d = 0; d < HD; d++) o[d] = fmaf(p, v_s[j * HD + d], o[d]);
    }
    __half* orow = &out[(size_t)(wi * NTOK + n) * CC + head * HD];
    #pragma unroll
    for (int i = 0; i < 8; i++) {
        float4 t = make_float4(o[i*4]*inv, o[i*4+1]*inv, o[i*4+2]*inv, o[i*4+3]*inv);
        *(uint2*)&orow[i * 4] = f4_to_h4(t);
    }
}

// ---------------- patch-merge gather + LN(512), half out --------------------
__global__ __launch_bounds__(128) void pm_ln_kernel(
    const float* __restrict__ x, const float* __restrict__ gam,
    const float* __restrict__ bet, __half* __restrict__ out)
{
    int lane = threadIdx.x & 31;
    int warp = threadIdx.x >> 5;
    int i = blockIdx.x * 4 + warp;
    int b = i / 2304, pos = i % 2304;
    int oh = pos / 48, ow = pos % 48;
    int base = b * LL;
    int src[4];
    src[0] = base + (2*oh    ) * WW + 2*ow;
    src[1] = base + (2*oh + 1) * WW + 2*ow;
    src[2] = base + (2*oh    ) * WW + 2*ow + 1;
    src[3] = base + (2*oh + 1) * WW + 2*ow + 1;
    float4 v[4];
    float s1 = 0.f, s2 = 0.f;
    #pragma unroll
    for (int k = 0; k < 4; k++) {
        v[k] = *(const float4*)&x[(size_t)src[k] * CC + lane * 4];
        s1 += v[k].x + v[k].y + v[k].z + v[k].w;
        s2 += v[k].x*v[k].x + v[k].y*v[k].y + v[k].z*v[k].z + v[k].w*v[k].w;
    }
    #pragma unroll
    for (int o = 16; o; o >>= 1) {
        s1 += __shfl_xor_sync(0xffffffffu, s1, o);
        s2 += __shfl_xor_sync(0xffffffffu, s2, o);
    }
    float mean = s1 * (1.f / 512.f);
    float var  = s2 * (1.f / 512.f) - mean * mean;
    float rstd = rsqrtf(var + 1e-5f);
    #pragma unroll
    for (int k = 0; k < 4; k++) {
        int col = k * CC + lane * 4;
        float4 g4 = *(const float4*)&gam[col];
        float4 b4 = *(const float4*)&bet[col];
        float4 o4;
        o4.x = (v[k].x - mean) * rstd * g4.x + b4.x;
        o4.y = (v[k].y - mean) * rstd * g4.y + b4.y;
        o4.z = (v[k].z - mean) * rstd * g4.z + b4.z;
        o4.w = (v[k].w - mean) * rstd * g4.w + b4.w;
        *(uint2*)&out[(size_t)i * 512 + col] = f4_to_h4(o4);
    }
}

// ---------------- host orchestration ----------------------------------------
static void run_block(const float* xin, float* xout, const float* const* p, int shift,
                      const __half* qkv_t, const __half* proj_t,
                      const __half* fc1_t, const __half* fc2_t,
                      __half* xw, __half* qkv, __half* att, __half* h)
{
    ln_kernel<true><<<ROWS/4, 128>>>(xin, p[0], p[1], xw, shift);
    gemm_mma<0,__half><<<dim3(ROWS/128, 3), 256, GM_SMEM>>>(xw, qkv_t, p[3], qkv, nullptr, ROWS, 384, CC, 0);
    attn_kernel<<<(ROWS/NTOK)*HEADS, 64>>>(qkv, att, shift > 0 ? 1 : 0);
    gemm_mma<1,float><<<dim3(ROWS/128, 1), 256, GM_SMEM>>>(att, proj_t, p[5], xout, xin, ROWS, CC, CC, shift);
    ln_kernel<false><<<ROWS/4, 128>>>(xout, p[6], p[7], xw, 0);
    gemm_mma<2,__half><<<dim3(ROWS/128, 4), 256, GM_SMEM>>>(xw, fc1_t, p[9], h, nullptr, ROWS, 512, CC, 0);
    gemm_mma<3,float><<<dim3(ROWS/128, 1), 256, GM_SMEM>>>(h, fc2_t, p[11], xout, xout, ROWS, CC, 512, 0);
}

extern "C" void kernel_launch(void* const* d_in, const int* in_sizes, int n_in,
                              void* d_out, int out_size)
{
    (void)in_sizes; (void)n_in; (void)out_size;
    const float* x = (const float*)d_in[0];
    const float* pa[12];
    const float* pb[12];
    for (int i = 0; i < 12; i++) pa[i] = (const float*)d_in[1 + i];
    for (int i = 0; i < 12; i++) pb[i] = (const float*)d_in[13 + i];
    const float* mln_g = (const float*)d_in[25];
    const float* mln_b = (const float*)d_in[26];
    const float* red_w = (const float*)d_in[27];
    float* out = (float*)d_out;

    __half *xw, *qkv, *att, *h, *wt;
    float *xa, *xb;
    cudaGetSymbolAddress((void**)&xw,  g_xw);
    cudaGetSymbolAddress((void**)&qkv, g_qkv);
    cudaGetSymbolAddress((void**)&att, g_att);
    cudaGetSymbolAddress((void**)&xa,  g_xa);
    cudaGetSymbolAddress((void**)&xb,  g_xb);
    cudaGetSymbolAddress((void**)&h,   g_h);
    cudaGetSymbolAddress((void**)&wt,  g_wt);

    __half* a_qkv_t  = wt;            // 384*128
    __half* a_proj_t = wt + 49152;    // 128*128
    __half* a_fc1_t  = wt + 65536;    // 512*128
    __half* a_fc2_t  = wt + 131072;   // 128*512
    __half* b_qkv_t  = wt + 196608;
    __half* b_proj_t = wt + 245760;
    __half* b_fc1_t  = wt + 262144;
    __half* b_fc2_t  = wt + 327680;
    __half* red_t    = wt + 393216;   // 256*512

    transpose_kernel<<<dim3(4, 12), 256>>>(pa[2],  a_qkv_t,  128, 384);
    transpose_kernel<<<dim3(4, 4),  256>>>(pa[4],  a_proj_t, 128, 128);
    transpose_kernel<<<dim3(4, 16), 256>>>(pa[8],  a_fc1_t,  128, 512);
    transpose_kernel<<<dim3(16, 4), 256>>>(pa[10], a_fc2_t,  512, 128);
    transpose_kernel<<<dim3(4, 12), 256>>>(pb[2],  b_qkv_t,  128, 384);
    transpose_kernel<<<dim3(4, 4),  256>>>(pb[4],  b_proj_t, 128, 128);
    transpose_kernel<<<dim3(4, 16), 256>>>(pb[8],  b_fc1_t,  128, 512);
    transpose_kernel<<<dim3(16, 4), 256>>>(pb[10], b_fc2_t,  512, 128);
    transpose_kernel<<<dim3(16, 8), 256>>>(red_w,  red_t,    512, 256);

    run_block(x,  xa, pa, 0, a_qkv_t, a_proj_t, a_fc1_t, a_fc2_t, xw, qkv, att, h);
    run_block(xa, xb, pb, 4, b_qkv_t, b_proj_t, b_fc1_t, b_fc2_t, xw, qkv, att, h);

    pm_ln_kernel<<<(ROWS/4)/NTOK * 16, 128>>>(xb, mln_g, mln_b, att);
    gemm_mma<4,float><<<dim3((ROWS/4)/128, 2), 256, GM_SMEM>>>(att, red_t, nullptr, out, nullptr,
                                                               ROWS/4, 256, 512, 0);
}